// round 1
// baseline (speedup 1.0000x reference)
#include <cuda_runtime.h>
#include <cstdint>

#define BATCH 16384
#define F 512
#define CSZ 16            // cluster size (CTAs), one per 32 output columns
#define NC (F/CSZ)        // 32 columns per CTA
#define NTHR 512
#define PF 6              // X prefetch distance
#define RING 8            // X smem ring depth

// ---------------- scratch for precomputed input projections ----------------
__device__ float g_Xz[(size_t)BATCH * F];   // x@Wz + bz
__device__ float g_Xh[(size_t)BATCH * F];   // x@Wh + bh

// ============================ GEMM (batch-parallel part) ====================
#define GBM 128
#define GBN 64
#define GBK 16

__global__ void __launch_bounds__(256) gemm_kernel(
    const float* __restrict__ A,
    const float* __restrict__ Wz, const float* __restrict__ bz,
    const float* __restrict__ Wh, const float* __restrict__ bh)
{
    const float* W    = blockIdx.z ? Wh : Wz;
    const float* bias = blockIdx.z ? bh : bz;
    float* out        = blockIdx.z ? g_Xh : g_Xz;

    __shared__ float As[GBK][GBM];
    __shared__ float Bs[GBK][GBN];

    const int tid  = threadIdx.x;
    const int row0 = blockIdx.y * GBM;
    const int col0 = blockIdx.x * GBN;
    const int ty = tid >> 4;        // 0..15
    const int tx = tid & 15;        // 0..15
    const int ar = tid >> 1;        // 0..127
    const int aseg = (tid & 1) * 8; // 0 or 8

    float acc[8][4];
#pragma unroll
    for (int i = 0; i < 8; i++)
#pragma unroll
        for (int j = 0; j < 4; j++) acc[i][j] = 0.f;

    for (int k0 = 0; k0 < F; k0 += GBK) {
        float4 av0 = *(const float4*)(A + (size_t)(row0 + ar) * F + k0 + aseg);
        float4 av1 = *(const float4*)(A + (size_t)(row0 + ar) * F + k0 + aseg + 4);
        float4 bv  = *(const float4*)(W + (size_t)(k0 + ty) * F + col0 + tx * 4);
        As[aseg+0][ar] = av0.x; As[aseg+1][ar] = av0.y;
        As[aseg+2][ar] = av0.z; As[aseg+3][ar] = av0.w;
        As[aseg+4][ar] = av1.x; As[aseg+5][ar] = av1.y;
        As[aseg+6][ar] = av1.z; As[aseg+7][ar] = av1.w;
        *(float4*)&Bs[ty][tx * 4] = bv;
        __syncthreads();
#pragma unroll
        for (int k = 0; k < GBK; k++) {
            float4 a0 = *(const float4*)&As[k][ty * 8];
            float4 a1 = *(const float4*)&As[k][ty * 8 + 4];
            float4 b  = *(const float4*)&Bs[k][tx * 4];
            float av[8] = {a0.x, a0.y, a0.z, a0.w, a1.x, a1.y, a1.z, a1.w};
            float bb[4] = {b.x, b.y, b.z, b.w};
#pragma unroll
            for (int i = 0; i < 8; i++)
#pragma unroll
                for (int j = 0; j < 4; j++) acc[i][j] += av[i] * bb[j];
        }
        __syncthreads();
    }

#pragma unroll
    for (int i = 0; i < 8; i++) {
        const int r = row0 + ty * 8 + i;
        float4 v;
        v.x = acc[i][0] + bias[col0 + tx * 4 + 0];
        v.y = acc[i][1] + bias[col0 + tx * 4 + 1];
        v.z = acc[i][2] + bias[col0 + tx * 4 + 2];
        v.w = acc[i][3] + bias[col0 + tx * 4 + 3];
        *(float4*)(out + (size_t)r * F + col0 + tx * 4) = v;
    }
}

// ======================= sequential recurrence (cluster) ====================

__device__ __forceinline__ unsigned smem_u32(const void* p) {
    return (unsigned)__cvta_generic_to_shared(p);
}

__global__ void __launch_bounds__(NTHR, 1) memrnn_kernel(
    const float* __restrict__ Uz, const float* __restrict__ Uh,
    float* __restrict__ out)
{
    __shared__ __align__(16) float mbuf[2][F];       // ping-pong full m vector
    __shared__ __align__(16) float mstage[2][NC];    // bulk-copy source (double buffered)
    __shared__ __align__(16) float part[64][8];      // partial dot sums
    __shared__ __align__(16) float xring[RING][2*NC];// [slot][0..31]=Xz chunk, [32..63]=Xh
    __shared__ __align__(8)  unsigned long long bars[2];

    const int tid = threadIdx.x;
    const int s = tid >> 6;   // k-slice 0..7
    const int d = tid & 63;   // dot index: 0..31 -> z cols, 32..63 -> h cols
    unsigned rank;
    asm("mov.u32 %0, %%cluster_ctarank;" : "=r"(rank));
    const int c = (int)rank;  // column block: cols [c*NC, c*NC+NC)

    // ---- load this thread's U slice into registers, packed for f32x2 ----
    const float* Usrc = (d < 32) ? (Uz + c * NC + d) : (Uh + c * NC + (d - 32));
    unsigned long long u[32];
#pragma unroll
    for (int i = 0; i < 32; i++) {
        float a0 = Usrc[(size_t)(s * 64 + 2 * i) * F];
        float a1 = Usrc[(size_t)(s * 64 + 2 * i + 1) * F];
        asm("mov.b64 %0, {%1, %2};" : "=l"(u[i]) : "f"(a0), "f"(a1));
    }

    mbuf[0][tid] = 0.f;   // m_0 = 0 (local copy; every CTA has its own full copy)

    const unsigned bar0 = smem_u32(&bars[0]);
    const unsigned bar1 = smem_u32(&bars[1]);
    const unsigned TXB = CSZ * NC * 4;   // 2048 bytes expected per phase

    if (tid == 0) {
        asm volatile("mbarrier.init.shared.b64 [%0], 1;" :: "r"(bar0) : "memory");
        asm volatile("mbarrier.init.shared.b64 [%0], 1;" :: "r"(bar1) : "memory");
        // arm first phase of both barriers
        asm volatile("mbarrier.arrive.expect_tx.shared.b64 _, [%0], %1;" :: "r"(bar0), "r"(TXB) : "memory");
        asm volatile("mbarrier.arrive.expect_tx.shared.b64 _, [%0], %1;" :: "r"(bar1), "r"(TXB) : "memory");
    }
    __syncthreads();
    asm volatile("barrier.cluster.arrive.aligned;" ::: "memory");
    asm volatile("barrier.cluster.wait.aligned;"   ::: "memory");

    // ---- X prefetch ring prologue (lanes 0..15 of warp 0) ----
    if (tid < 16) {
        for (int p = 0; p < PF; p++) {
            const float* g = (tid < 8)
                ? (g_Xz + (size_t)p * F + c * NC + tid * 4)
                : (g_Xh + (size_t)p * F + c * NC + (tid - 8) * 4);
            unsigned sa = smem_u32(&xring[p][(tid < 8) ? tid * 4 : 32 + (tid - 8) * 4]);
            asm volatile("cp.async.cg.shared.global [%0], [%1], 16;" :: "r"(sa), "l"(g));
            asm volatile("cp.async.commit_group;");
        }
    }

    int ph0 = 0, ph1 = 0;

    for (int t = 0; t < BATCH; t++) {
        const int rb = t & 1;
        const int wb = rb ^ 1;

        // ---------- partial dot products: all 512 threads ----------
        const float* mp = mbuf[rb] + s * 64;
        unsigned long long a0 = 0ull, a1 = 0ull;
#pragma unroll
        for (int i = 0; i < 16; i++) {
            ulonglong2 mv = *(const ulonglong2*)(mp + i * 4);   // broadcast LDS.128
            asm("fma.rn.f32x2 %0, %1, %2, %0;" : "+l"(a0) : "l"(mv.x), "l"(u[2 * i]));
            asm("fma.rn.f32x2 %0, %1, %2, %0;" : "+l"(a1) : "l"(mv.y), "l"(u[2 * i + 1]));
        }
        float lo0, hi0, lo1, hi1;
        asm("mov.b64 {%0, %1}, %2;" : "=f"(lo0), "=f"(hi0) : "l"(a0));
        asm("mov.b64 {%0, %1}, %2;" : "=f"(lo1), "=f"(hi1) : "l"(a1));
        part[d][s] = (lo0 + hi0) + (lo1 + hi1);
        __syncthreads();

        // ---------- warp 0: reduce, gates, output, broadcast ----------
        if (tid < 32) {
            if (tid < 16) {
                if (t + PF < BATCH) {
                    const float* g = (tid < 8)
                        ? (g_Xz + (size_t)(t + PF) * F + c * NC + tid * 4)
                        : (g_Xh + (size_t)(t + PF) * F + c * NC + (tid - 8) * 4);
                    unsigned sa = smem_u32(&xring[(t + PF) % RING]
                                           [(tid < 8) ? tid * 4 : 32 + (tid - 8) * 4]);
                    asm volatile("cp.async.cg.shared.global [%0], [%1], 16;" :: "r"(sa), "l"(g));
                }
                asm volatile("cp.async.commit_group;");   // empty groups near the tail keep the count honest
                asm volatile("cp.async.wait_group 6;");   // slot t is now complete
            }
            __syncwarp();

            const int j = tid;  // output column within chunk
            float4 p0 = *(const float4*)&part[j][0];
            float4 p1 = *(const float4*)&part[j][4];
            float4 q0 = *(const float4*)&part[32 + j][0];
            float4 q1 = *(const float4*)&part[32 + j][4];
            float zs = ((p0.x + p0.y) + (p0.z + p0.w)) + ((p1.x + p1.y) + (p1.z + p1.w))
                       + xring[t % RING][j];
            float hs = ((q0.x + q0.y) + (q0.z + q0.w)) + ((q1.x + q1.y) + (q1.z + q1.w))
                       + xring[t % RING][32 + j];
            float mo = mbuf[rb][c * NC + j];
            float z  = 1.0f / (1.0f + __expf(-zs));
            float h  = 2.0f / (1.0f + __expf(-2.0f * hs)) - 1.0f;   // tanh, saturates correctly
            float mn = mo + z * (h - mo);
            out[(size_t)t * F + c * NC + j] = mn;

            if (t + 1 < BATCH) {
                mstage[rb][j] = mn;
                asm volatile("fence.proxy.async.shared::cta;" ::: "memory");
                __syncwarp();
                if (tid == 0) {
                    unsigned src  = smem_u32(&mstage[rb][0]);
                    unsigned ldst = smem_u32(&mbuf[wb][c * NC]);
                    unsigned lbar = wb ? bar1 : bar0;
#pragma unroll
                    for (int r = 0; r < CSZ; r++) {
                        unsigned rdst, rbar;
                        asm("mapa.shared::cluster.u32 %0, %1, %2;" : "=r"(rdst) : "r"(ldst), "r"(r));
                        asm("mapa.shared::cluster.u32 %0, %1, %2;" : "=r"(rbar) : "r"(lbar), "r"(r));
                        asm volatile(
                            "cp.async.bulk.shared::cluster.shared::cta.mbarrier::complete_tx::bytes "
                            "[%0], [%1], %2, [%3];"
                            :: "r"(rdst), "r"(src), "r"(NC * 4), "r"(rbar) : "memory");
                    }
                }
            }
        }

        // ---------- all threads: wait for the full m_{t+1} ----------
        if (t + 1 < BATCH) {
            unsigned bar = wb ? bar1 : bar0;
            int par = wb ? ph1 : ph0;
            asm volatile(
                "{\n\t.reg .pred P;\n"
                "W_%=: mbarrier.try_wait.parity.acquire.cluster.shared::cta.b64 P, [%0], %1, 0x989680;\n\t"
                "@!P bra W_%=;\n\t}"
                :: "r"(bar), "r"(par) : "memory");
            if (wb) ph1 ^= 1; else ph0 ^= 1;
            if (tid == 0) {   // re-arm this barrier for its next use (step t+2)
                asm volatile("mbarrier.arrive.expect_tx.shared.b64 _, [%0], %1;"
                             :: "r"(bar), "r"(TXB) : "memory");
            }
        }
    }

    asm volatile("barrier.cluster.arrive.aligned;" ::: "memory");
    asm volatile("barrier.cluster.wait.aligned;"   ::: "memory");
}

// ================================ launch ====================================
extern "C" void kernel_launch(void* const* d_in, const int* in_sizes, int n_in,
                              void* d_out, int out_size)
{
    const float* x  = (const float*)d_in[0];
    const float* Wz = (const float*)d_in[1];
    const float* Uz = (const float*)d_in[2];
    const float* bz = (const float*)d_in[3];
    const float* Wh = (const float*)d_in[4];
    const float* Uh = (const float*)d_in[5];
    const float* bh = (const float*)d_in[6];
    float* out = (float*)d_out;

    // 1) batch-parallel input projections
    dim3 ggrid(F / GBN, BATCH / GBM, 2);
    gemm_kernel<<<ggrid, 256>>>(x, Wz, bz, Wh, bh);

    // 2) sequential recurrence on a 16-CTA cluster
    cudaFuncSetAttribute((const void*)memrnn_kernel,
                         cudaFuncAttributeNonPortableClusterSizeAllowed, 1);

    cudaLaunchConfig_t cfg = {};
    cfg.gridDim  = dim3(CSZ, 1, 1);
    cfg.blockDim = dim3(NTHR, 1, 1);
    cfg.dynamicSmemBytes = 0;
    cfg.stream = 0;
    cudaLaunchAttribute attrs[1];
    attrs[0].id = cudaLaunchAttributeClusterDimension;
    attrs[0].val.clusterDim.x = CSZ;
    attrs[0].val.clusterDim.y = 1;
    attrs[0].val.clusterDim.z = 1;
    cfg.attrs = attrs;
    cfg.numAttrs = 1;

    cudaLaunchKernelEx(&cfg, memrnn_kernel, Uz, Uh, out);
}